// round 15
// baseline (speedup 1.0000x reference)
#include <cuda_runtime.h>

#define NG      512
#define W_IMG   256
#define H_IMG   256
#define NEG_HALF_LOG2E (-0.7213475204444817f)   // -0.5 * log2(e)
#define LOG2EPS (-27.0f)                        // skip if max alpha < 2^-27

__device__ __forceinline__ float ex2_approx(float x) {
    float y; asm("ex2.approx.f32 %0, %1;" : "=f"(y) : "f"(x)); return y;
}
__device__ __forceinline__ float lg2_approx(float x) {
    float y; asm("lg2.approx.f32 %0, %1;" : "=f"(y) : "f"(x)); return y;
}
__device__ __forceinline__ float rcp_approx(float x) {
    float y; asm("rcp.approx.f32 %0, %1;" : "=f"(y) : "f"(x)); return y;
}

// One block per row, 256 threads = 4 groups × 64; each thread composites an
// ordered quarter of the survivors for 4 adjacent pixels (second-difference
// exponent). Prep culls per (gaussian, x-half) with the clamped-vertex window
// test and builds TWO ordered compacted lists (px[0,128) / px[128,256)); a
// warp's lanes lie entirely in one half, so the mainloop iterates only its
// half's list — no per-iteration vote. Global loads are front-batched for MLP;
// mainloop processes 2 gaussians per step (batched LDS). Partials combined
// exactly (compositing is an associative affine map).
__global__ __launch_bounds__(256) void Render_75617194213733_kernel(
    const float* __restrict__ means,    // [NG,2]
    const float* __restrict__ cov,      // [NG,2,2]
    const float* __restrict__ opac,     // [NG]
    const float* __restrict__ colors,   // [NG,3]
    float* __restrict__ out)            // [H,W,3]
{
    __shared__ float4 C[4 * NG];        // half0 at 0, half1 at 2*NG:
                                        // [2j]=(mx,ka,kb*dy,kd*dy^2+lop), [2j+1]=(cr,cg,cb,2ka)
    __shared__ float4 Ppart[4][3 * 64]; // per-pixel partials, groups 1..3
    __shared__ int    sCnt0[16], sCnt1[16];
    __shared__ int    sBase0[16], sBase1[16];
    __shared__ int    sM0, sM1;

    const int tid  = threadIdx.x;
    const int lane = tid & 31;
    const int warp = tid >> 5;
    const float py = (float)blockIdx.x + 0.5f;

    // ── Front-batched global loads for both gaussian chunks (max MLP).
    const int g0i = tid, g1i = tid + 256;
    float4 cv_[2];
    float2 mn_[2];
    float  op_[2];
    float  cr_[2], cg_[2], cb_[2];
    cv_[0] = ((const float4*)cov)[g0i];
    cv_[1] = ((const float4*)cov)[g1i];
    mn_[0] = ((const float2*)means)[g0i];
    mn_[1] = ((const float2*)means)[g1i];
    op_[0] = opac[g0i];
    op_[1] = opac[g1i];
    cr_[0] = colors[3 * g0i + 0]; cg_[0] = colors[3 * g0i + 1]; cb_[0] = colors[3 * g0i + 2];
    cr_[1] = colors[3 * g1i + 0]; cg_[1] = colors[3 * g1i + 1]; cb_[1] = colors[3 * g1i + 2];

    // ── Fused prep + per-half x-window cull (2 gaussians/thread).
    float4 A[2], B[2];
    bool   kp0[2], kp1[2];
    unsigned b0[2], b1[2];
#pragma unroll
    for (int c = 0; c < 2; c++) {
        float4 cv = cv_[c];
        float2 mn = mn_[c];
        float det = fmaf(cv.x, cv.w, -cv.y * cv.z);
        float s   = NEG_HALF_LOG2E * rcp_approx(det);
        float ka  = s * cv.w;                          // < 0
        float kb  = -s * (cv.y + cv.z);
        float kd  = s * cv.x;                          // < 0
        float lop = lg2_approx(op_[c]);
        float dy  = py - mn.y;
        float kbdy = kb * dy;
        float c1   = fmaf(kd * dy, dy, lop);           // kd*dy^2 + log2(op)
        // max of m(dx)=ka*dx^2+kbdy*dx+c1 over each half's x-window:
        // vertex dx* = -kbdy/(2ka) (ka<0 ⇒ max), clamped per window.
        float dxv = -kbdy * rcp_approx(ka + ka);
        float d0 = fminf(fmaxf(dxv, 0.5f - mn.x),   127.5f - mn.x);
        float d1 = fminf(fmaxf(dxv, 128.5f - mn.x), 255.5f - mn.x);
        kp0[c] = fmaf(fmaf(ka, d0, kbdy), d0, c1) > LOG2EPS;
        kp1[c] = fmaf(fmaf(ka, d1, kbdy), d1, c1) > LOG2EPS;
        b0[c] = __ballot_sync(0xffffffffu, kp0[c]);
        b1[c] = __ballot_sync(0xffffffffu, kp1[c]);
        if (lane == 0) {
            sCnt0[c * 8 + warp] = __popc(b0[c]);
            sCnt1[c * 8 + warp] = __popc(b1[c]);
        }
        A[c] = make_float4(mn.x, ka, kbdy, c1);
        B[c] = make_float4(cr_[c], cg_[c], cb_[c], ka + ka);
    }
    __syncthreads();

    // ── Parallel shuffle scans: warp 0 -> half0 counts, warp 1 -> half1.
    if (warp < 2) {
        const int* cnt = warp ? sCnt1 : sCnt0;
        int* bas = warp ? sBase1 : sBase0;
        int c = (lane < 16) ? cnt[lane] : 0;
        int inc = c;
#pragma unroll
        for (int d = 1; d < 16; d <<= 1) {
            int n = __shfl_up_sync(0xffffffffu, inc, d);
            if (lane >= d) inc += n;
        }
        if (lane < 16) bas[lane] = inc - c;
        if (lane == 15) { if (warp) sM1 = inc; else sM0 = inc; }
    }
    __syncthreads();

#pragma unroll
    for (int c = 0; c < 2; c++) {
        const unsigned lm = (1u << lane) - 1u;
        if (kp0[c]) {
            int j = sBase0[c * 8 + warp] + __popc(b0[c] & lm);
            C[2 * j]     = A[c];
            C[2 * j + 1] = B[c];
        }
        if (kp1[c]) {
            int j = sBase1[c * 8 + warp] + __popc(b1[c] & lm);
            C[2 * NG + 2 * j]     = A[c];
            C[2 * NG + 2 * j + 1] = B[c];
        }
    }
    __syncthreads();

    // ── Mainloop: warp's lanes span one 128-px half; iterate that half's list.
    const int half  = warp & 1;                 // even warp ⇔ t<32 ⇔ px<128
    const int M     = half ? sM1 : sM0;
    const float4* __restrict__ Ch = C + half * (2 * NG);
    const int Mq    = (M + 3) >> 2;
    const int group = tid >> 6;
    const int t     = tid & 63;
    const int j0    = min(group * Mq, M);
    const int j1    = min(j0 + Mq, M);

    const float px = (float)(4 * t) + 0.5f;

    float T0 = 1.f, T1 = 1.f, T2 = 1.f, T3 = 1.f;
    float r0 = 0.f, g0 = 0.f, u0 = 0.f;
    float r1 = 0.f, g1 = 0.f, u1 = 0.f;
    float r2 = 0.f, g2 = 0.f, u2 = 0.f;
    float r3 = 0.f, g3 = 0.f, u3 = 0.f;

    int j = j0;
    for (; j + 1 < j1; j += 2) {
        // 4 × LDS.128 issued back-to-back (2× MLP on the LDS path).
        float4 paA = Ch[2 * j],     pbA = Ch[2 * j + 1];
        float4 paB = Ch[2 * j + 2], pbB = Ch[2 * j + 3];

        float dxA = px - paA.x;
        float t2A = fmaf(paA.y, dxA, paA.z);
        float m0A = fmaf(dxA, t2A, paA.w);
        float s0A = t2A + fmaf(paA.y, dxA, paA.y);
        float m1A = m0A + s0A;
        float s1A = s0A + pbA.w;
        float m2A = m1A + s1A;
        float m3A = m2A + s1A + pbA.w;

        float a0 = ex2_approx(m0A), a1 = ex2_approx(m1A);
        float a2 = ex2_approx(m2A), a3 = ex2_approx(m3A);
        float w0 = a0 * T0, w1 = a1 * T1, w2 = a2 * T2, w3 = a3 * T3;
        r0 = fmaf(w0, pbA.x, r0); g0 = fmaf(w0, pbA.y, g0); u0 = fmaf(w0, pbA.z, u0);
        r1 = fmaf(w1, pbA.x, r1); g1 = fmaf(w1, pbA.y, g1); u1 = fmaf(w1, pbA.z, u1);
        r2 = fmaf(w2, pbA.x, r2); g2 = fmaf(w2, pbA.y, g2); u2 = fmaf(w2, pbA.z, u2);
        r3 = fmaf(w3, pbA.x, r3); g3 = fmaf(w3, pbA.y, g3); u3 = fmaf(w3, pbA.z, u3);
        T0 *= 1.0000001f - a0;
        T1 *= 1.0000001f - a1;
        T2 *= 1.0000001f - a2;
        T3 *= 1.0000001f - a3;

        float dxB = px - paB.x;
        float t2B = fmaf(paB.y, dxB, paB.z);
        float m0B = fmaf(dxB, t2B, paB.w);
        float s0B = t2B + fmaf(paB.y, dxB, paB.y);
        float m1B = m0B + s0B;
        float s1B = s0B + pbB.w;
        float m2B = m1B + s1B;
        float m3B = m2B + s1B + pbB.w;

        float e0 = ex2_approx(m0B), e1 = ex2_approx(m1B);
        float e2 = ex2_approx(m2B), e3 = ex2_approx(m3B);
        float v0 = e0 * T0, v1 = e1 * T1, v2 = e2 * T2, v3 = e3 * T3;
        r0 = fmaf(v0, pbB.x, r0); g0 = fmaf(v0, pbB.y, g0); u0 = fmaf(v0, pbB.z, u0);
        r1 = fmaf(v1, pbB.x, r1); g1 = fmaf(v1, pbB.y, g1); u1 = fmaf(v1, pbB.z, u1);
        r2 = fmaf(v2, pbB.x, r2); g2 = fmaf(v2, pbB.y, g2); u2 = fmaf(v2, pbB.z, u2);
        r3 = fmaf(v3, pbB.x, r3); g3 = fmaf(v3, pbB.y, g3); u3 = fmaf(v3, pbB.z, u3);
        T0 *= 1.0000001f - e0;
        T1 *= 1.0000001f - e1;
        T2 *= 1.0000001f - e2;
        T3 *= 1.0000001f - e3;
    }
    if (j < j1) {
        float4 pa = Ch[2 * j], pb = Ch[2 * j + 1];
        float dx = px - pa.x;
        float t2 = fmaf(pa.y, dx, pa.z);
        float m0 = fmaf(dx, t2, pa.w);
        float s0 = t2 + fmaf(pa.y, dx, pa.y);
        float m1 = m0 + s0;
        float s1 = s0 + pb.w;
        float m2 = m1 + s1;
        float m3 = m2 + s1 + pb.w;
        float a0 = ex2_approx(m0), a1 = ex2_approx(m1);
        float a2 = ex2_approx(m2), a3 = ex2_approx(m3);
        float w0 = a0 * T0, w1 = a1 * T1, w2 = a2 * T2, w3 = a3 * T3;
        r0 = fmaf(w0, pb.x, r0); g0 = fmaf(w0, pb.y, g0); u0 = fmaf(w0, pb.z, u0);
        r1 = fmaf(w1, pb.x, r1); g1 = fmaf(w1, pb.y, g1); u1 = fmaf(w1, pb.z, u1);
        r2 = fmaf(w2, pb.x, r2); g2 = fmaf(w2, pb.y, g2); u2 = fmaf(w2, pb.z, u2);
        r3 = fmaf(w3, pb.x, r3); g3 = fmaf(w3, pb.y, g3); u3 = fmaf(w3, pb.z, u3);
        T0 *= 1.0000001f - a0;
        T1 *= 1.0000001f - a1;
        T2 *= 1.0000001f - a2;
        T3 *= 1.0000001f - a3;
    }

    // ── Exact segment combine: C = C_a + T_a * C_b (fold groups 3→2→1→0).
    if (group != 0) {
        int pi = (group - 1) * 64 + t;
        Ppart[0][pi] = make_float4(r0, g0, u0, T0);
        Ppart[1][pi] = make_float4(r1, g1, u1, T1);
        Ppart[2][pi] = make_float4(r2, g2, u2, T2);
        Ppart[3][pi] = make_float4(r3, g3, u3, T3);
    }
    __syncthreads();
    if (group == 0) {
        float rl[4] = {r0, r1, r2, r3};
        float gl[4] = {g0, g1, g2, g3};
        float bl[4] = {u0, u1, u2, u3};
        float Tl[4] = {T0, T1, T2, T3};
        float R[4], G[4], B[4];
#pragma unroll
        for (int p = 0; p < 4; p++) {
            float4 q1 = Ppart[p][t];
            float4 q2 = Ppart[p][64 + t];
            float4 q3 = Ppart[p][128 + t];
            float rr = fmaf(q2.w, q3.x, q2.x);
            float gg = fmaf(q2.w, q3.y, q2.y);
            float bb = fmaf(q2.w, q3.z, q2.z);
            rr = fmaf(q1.w, rr, q1.x);
            gg = fmaf(q1.w, gg, q1.y);
            bb = fmaf(q1.w, bb, q1.z);
            R[p] = fmaf(Tl[p], rr, rl[p]);
            G[p] = fmaf(Tl[p], gg, gl[p]);
            B[p] = fmaf(Tl[p], bb, bl[p]);
        }
        float4* o4 = (float4*)(out + (blockIdx.x * W_IMG + 4 * t) * 3);
        o4[0] = make_float4(R[0], G[0], B[0], R[1]);
        o4[1] = make_float4(G[1], B[1], R[2], G[2]);
        o4[2] = make_float4(B[2], R[3], G[3], B[3]);
    }
}

extern "C" void kernel_launch(void* const* d_in, const int* in_sizes, int n_in,
                              void* d_out, int out_size) {
    const float* means  = nullptr;
    const float* cov    = nullptr;
    const float* opac   = nullptr;
    const float* colors = nullptr;
    for (int i = 0; i < n_in; i++) {
        switch (in_sizes[i]) {
            case NG * 2: means  = (const float*)d_in[i]; break;
            case NG * 4: cov    = (const float*)d_in[i]; break;
            case NG:     opac   = (const float*)d_in[i]; break;
            case NG * 3: colors = (const float*)d_in[i]; break;
            default: break;
        }
    }
    Render_75617194213733_kernel<<<H_IMG, 256>>>(means, cov, opac, colors,
                                                 (float*)d_out);
}

// round 16
// speedup vs baseline: 1.0036x; 1.0036x over previous
#include <cuda_runtime.h>

#define NG      512
#define W_IMG   256
#define H_IMG   256
#define NEG_HALF_LOG2E (-0.7213475204444817f)   // -0.5 * log2(e)
#define LOG2EPS (-16.0f)                        // skip if max alpha < 2^-16 (~1.5e-5)
// Error audit: the dominant cull error is the dropped deterministic +1e-7 in
// (1-a+1e-7) for culled gaussians (~#culled * 1e-7 ≈ 5e-5, threshold-
// independent). The alpha-mass term at 2^-16 adds ~<1e-4 rel — total well
// under the 1e-3 gate, and the tighter radius cuts survivors ~25%.

__device__ __forceinline__ float ex2_approx(float x) {
    float y; asm("ex2.approx.f32 %0, %1;" : "=f"(y) : "f"(x)); return y;
}
__device__ __forceinline__ float lg2_approx(float x) {
    float y; asm("lg2.approx.f32 %0, %1;" : "=f"(y) : "f"(x)); return y;
}
__device__ __forceinline__ float rcp_approx(float x) {
    float y; asm("rcp.approx.f32 %0, %1;" : "=f"(y) : "f"(x)); return y;
}

// One block per row, 256 threads = 4 groups × 64; each thread composites an
// ordered quarter of the survivors for 4 adjacent pixels (second-difference
// exponent). Prep culls per (gaussian, x-half) with the clamped-vertex window
// test and builds TWO ordered compacted lists (px[0,128) / px[128,256)); a
// warp's lanes lie entirely in one half, so the mainloop iterates only its
// half's list — no per-iteration vote. Global loads are front-batched for MLP;
// mainloop processes 2 gaussians per step (batched LDS). Partials combined
// exactly (compositing is an associative affine map).
__global__ __launch_bounds__(256) void Render_75617194213733_kernel(
    const float* __restrict__ means,    // [NG,2]
    const float* __restrict__ cov,      // [NG,2,2]
    const float* __restrict__ opac,     // [NG]
    const float* __restrict__ colors,   // [NG,3]
    float* __restrict__ out)            // [H,W,3]
{
    __shared__ float4 C[4 * NG];        // half0 at 0, half1 at 2*NG:
                                        // [2j]=(mx,ka,kb*dy,kd*dy^2+lop), [2j+1]=(cr,cg,cb,2ka)
    __shared__ float4 Ppart[4][3 * 64]; // per-pixel partials, groups 1..3
    __shared__ int    sCnt0[16], sCnt1[16];
    __shared__ int    sBase0[16], sBase1[16];
    __shared__ int    sM0, sM1;

    const int tid  = threadIdx.x;
    const int lane = tid & 31;
    const int warp = tid >> 5;
    const float py = (float)blockIdx.x + 0.5f;

    // ── Front-batched global loads for both gaussian chunks (max MLP).
    const int g0i = tid, g1i = tid + 256;
    float4 cv_[2];
    float2 mn_[2];
    float  op_[2];
    float  cr_[2], cg_[2], cb_[2];
    cv_[0] = ((const float4*)cov)[g0i];
    cv_[1] = ((const float4*)cov)[g1i];
    mn_[0] = ((const float2*)means)[g0i];
    mn_[1] = ((const float2*)means)[g1i];
    op_[0] = opac[g0i];
    op_[1] = opac[g1i];
    cr_[0] = colors[3 * g0i + 0]; cg_[0] = colors[3 * g0i + 1]; cb_[0] = colors[3 * g0i + 2];
    cr_[1] = colors[3 * g1i + 0]; cg_[1] = colors[3 * g1i + 1]; cb_[1] = colors[3 * g1i + 2];

    // ── Fused prep + per-half x-window cull (2 gaussians/thread).
    float4 A[2], B[2];
    bool   kp0[2], kp1[2];
    unsigned b0[2], b1[2];
#pragma unroll
    for (int c = 0; c < 2; c++) {
        float4 cv = cv_[c];
        float2 mn = mn_[c];
        float det = fmaf(cv.x, cv.w, -cv.y * cv.z);
        float s   = NEG_HALF_LOG2E * rcp_approx(det);
        float ka  = s * cv.w;                          // < 0
        float kb  = -s * (cv.y + cv.z);
        float kd  = s * cv.x;                          // < 0
        float lop = lg2_approx(op_[c]);
        float dy  = py - mn.y;
        float kbdy = kb * dy;
        float c1   = fmaf(kd * dy, dy, lop);           // kd*dy^2 + log2(op)
        // max of m(dx)=ka*dx^2+kbdy*dx+c1 over each half's x-window:
        // vertex dx* = -kbdy/(2ka) (ka<0 ⇒ max), clamped per window.
        float dxv = -kbdy * rcp_approx(ka + ka);
        float d0 = fminf(fmaxf(dxv, 0.5f - mn.x),   127.5f - mn.x);
        float d1 = fminf(fmaxf(dxv, 128.5f - mn.x), 255.5f - mn.x);
        kp0[c] = fmaf(fmaf(ka, d0, kbdy), d0, c1) > LOG2EPS;
        kp1[c] = fmaf(fmaf(ka, d1, kbdy), d1, c1) > LOG2EPS;
        b0[c] = __ballot_sync(0xffffffffu, kp0[c]);
        b1[c] = __ballot_sync(0xffffffffu, kp1[c]);
        if (lane == 0) {
            sCnt0[c * 8 + warp] = __popc(b0[c]);
            sCnt1[c * 8 + warp] = __popc(b1[c]);
        }
        A[c] = make_float4(mn.x, ka, kbdy, c1);
        B[c] = make_float4(cr_[c], cg_[c], cb_[c], ka + ka);
    }
    __syncthreads();

    // ── Parallel shuffle scans: warp 0 -> half0 counts, warp 1 -> half1.
    if (warp < 2) {
        const int* cnt = warp ? sCnt1 : sCnt0;
        int* bas = warp ? sBase1 : sBase0;
        int c = (lane < 16) ? cnt[lane] : 0;
        int inc = c;
#pragma unroll
        for (int d = 1; d < 16; d <<= 1) {
            int n = __shfl_up_sync(0xffffffffu, inc, d);
            if (lane >= d) inc += n;
        }
        if (lane < 16) bas[lane] = inc - c;
        if (lane == 15) { if (warp) sM1 = inc; else sM0 = inc; }
    }
    __syncthreads();

#pragma unroll
    for (int c = 0; c < 2; c++) {
        const unsigned lm = (1u << lane) - 1u;
        if (kp0[c]) {
            int j = sBase0[c * 8 + warp] + __popc(b0[c] & lm);
            C[2 * j]     = A[c];
            C[2 * j + 1] = B[c];
        }
        if (kp1[c]) {
            int j = sBase1[c * 8 + warp] + __popc(b1[c] & lm);
            C[2 * NG + 2 * j]     = A[c];
            C[2 * NG + 2 * j + 1] = B[c];
        }
    }
    __syncthreads();

    // ── Mainloop: warp's lanes span one 128-px half; iterate that half's list.
    const int half  = warp & 1;                 // even warp ⇔ t<32 ⇔ px<128
    const int M     = half ? sM1 : sM0;
    const float4* __restrict__ Ch = C + half * (2 * NG);
    const int Mq    = (M + 3) >> 2;
    const int group = tid >> 6;
    const int t     = tid & 63;
    const int j0    = min(group * Mq, M);
    const int j1    = min(j0 + Mq, M);

    const float px = (float)(4 * t) + 0.5f;

    float T0 = 1.f, T1 = 1.f, T2 = 1.f, T3 = 1.f;
    float r0 = 0.f, g0 = 0.f, u0 = 0.f;
    float r1 = 0.f, g1 = 0.f, u1 = 0.f;
    float r2 = 0.f, g2 = 0.f, u2 = 0.f;
    float r3 = 0.f, g3 = 0.f, u3 = 0.f;

    int j = j0;
    for (; j + 1 < j1; j += 2) {
        // 4 × LDS.128 issued back-to-back (2× MLP on the LDS path).
        float4 paA = Ch[2 * j],     pbA = Ch[2 * j + 1];
        float4 paB = Ch[2 * j + 2], pbB = Ch[2 * j + 3];

        float dxA = px - paA.x;
        float t2A = fmaf(paA.y, dxA, paA.z);
        float m0A = fmaf(dxA, t2A, paA.w);
        float s0A = t2A + fmaf(paA.y, dxA, paA.y);
        float m1A = m0A + s0A;
        float s1A = s0A + pbA.w;
        float m2A = m1A + s1A;
        float m3A = m2A + s1A + pbA.w;

        float a0 = ex2_approx(m0A), a1 = ex2_approx(m1A);
        float a2 = ex2_approx(m2A), a3 = ex2_approx(m3A);
        float w0 = a0 * T0, w1 = a1 * T1, w2 = a2 * T2, w3 = a3 * T3;
        r0 = fmaf(w0, pbA.x, r0); g0 = fmaf(w0, pbA.y, g0); u0 = fmaf(w0, pbA.z, u0);
        r1 = fmaf(w1, pbA.x, r1); g1 = fmaf(w1, pbA.y, g1); u1 = fmaf(w1, pbA.z, u1);
        r2 = fmaf(w2, pbA.x, r2); g2 = fmaf(w2, pbA.y, g2); u2 = fmaf(w2, pbA.z, u2);
        r3 = fmaf(w3, pbA.x, r3); g3 = fmaf(w3, pbA.y, g3); u3 = fmaf(w3, pbA.z, u3);
        T0 *= 1.0000001f - a0;
        T1 *= 1.0000001f - a1;
        T2 *= 1.0000001f - a2;
        T3 *= 1.0000001f - a3;

        float dxB = px - paB.x;
        float t2B = fmaf(paB.y, dxB, paB.z);
        float m0B = fmaf(dxB, t2B, paB.w);
        float s0B = t2B + fmaf(paB.y, dxB, paB.y);
        float m1B = m0B + s0B;
        float s1B = s0B + pbB.w;
        float m2B = m1B + s1B;
        float m3B = m2B + s1B + pbB.w;

        float e0 = ex2_approx(m0B), e1 = ex2_approx(m1B);
        float e2 = ex2_approx(m2B), e3 = ex2_approx(m3B);
        float v0 = e0 * T0, v1 = e1 * T1, v2 = e2 * T2, v3 = e3 * T3;
        r0 = fmaf(v0, pbB.x, r0); g0 = fmaf(v0, pbB.y, g0); u0 = fmaf(v0, pbB.z, u0);
        r1 = fmaf(v1, pbB.x, r1); g1 = fmaf(v1, pbB.y, g1); u1 = fmaf(v1, pbB.z, u1);
        r2 = fmaf(v2, pbB.x, r2); g2 = fmaf(v2, pbB.y, g2); u2 = fmaf(v2, pbB.z, u2);
        r3 = fmaf(v3, pbB.x, r3); g3 = fmaf(v3, pbB.y, g3); u3 = fmaf(v3, pbB.z, u3);
        T0 *= 1.0000001f - e0;
        T1 *= 1.0000001f - e1;
        T2 *= 1.0000001f - e2;
        T3 *= 1.0000001f - e3;
    }
    if (j < j1) {
        float4 pa = Ch[2 * j], pb = Ch[2 * j + 1];
        float dx = px - pa.x;
        float t2 = fmaf(pa.y, dx, pa.z);
        float m0 = fmaf(dx, t2, pa.w);
        float s0 = t2 + fmaf(pa.y, dx, pa.y);
        float m1 = m0 + s0;
        float s1 = s0 + pb.w;
        float m2 = m1 + s1;
        float m3 = m2 + s1 + pb.w;
        float a0 = ex2_approx(m0), a1 = ex2_approx(m1);
        float a2 = ex2_approx(m2), a3 = ex2_approx(m3);
        float w0 = a0 * T0, w1 = a1 * T1, w2 = a2 * T2, w3 = a3 * T3;
        r0 = fmaf(w0, pb.x, r0); g0 = fmaf(w0, pb.y, g0); u0 = fmaf(w0, pb.z, u0);
        r1 = fmaf(w1, pb.x, r1); g1 = fmaf(w1, pb.y, g1); u1 = fmaf(w1, pb.z, u1);
        r2 = fmaf(w2, pb.x, r2); g2 = fmaf(w2, pb.y, g2); u2 = fmaf(w2, pb.z, u2);
        r3 = fmaf(w3, pb.x, r3); g3 = fmaf(w3, pb.y, g3); u3 = fmaf(w3, pb.z, u3);
        T0 *= 1.0000001f - a0;
        T1 *= 1.0000001f - a1;
        T2 *= 1.0000001f - a2;
        T3 *= 1.0000001f - a3;
    }

    // ── Exact segment combine: C = C_a + T_a * C_b (fold groups 3→2→1→0).
    if (group != 0) {
        int pi = (group - 1) * 64 + t;
        Ppart[0][pi] = make_float4(r0, g0, u0, T0);
        Ppart[1][pi] = make_float4(r1, g1, u1, T1);
        Ppart[2][pi] = make_float4(r2, g2, u2, T2);
        Ppart[3][pi] = make_float4(r3, g3, u3, T3);
    }
    __syncthreads();
    if (group == 0) {
        float rl[4] = {r0, r1, r2, r3};
        float gl[4] = {g0, g1, g2, g3};
        float bl[4] = {u0, u1, u2, u3};
        float Tl[4] = {T0, T1, T2, T3};
        float R[4], G[4], B[4];
#pragma unroll
        for (int p = 0; p < 4; p++) {
            float4 q1 = Ppart[p][t];
            float4 q2 = Ppart[p][64 + t];
            float4 q3 = Ppart[p][128 + t];
            float rr = fmaf(q2.w, q3.x, q2.x);
            float gg = fmaf(q2.w, q3.y, q2.y);
            float bb = fmaf(q2.w, q3.z, q2.z);
            rr = fmaf(q1.w, rr, q1.x);
            gg = fmaf(q1.w, gg, q1.y);
            bb = fmaf(q1.w, bb, q1.z);
            R[p] = fmaf(Tl[p], rr, rl[p]);
            G[p] = fmaf(Tl[p], gg, gl[p]);
            B[p] = fmaf(Tl[p], bb, bl[p]);
        }
        float4* o4 = (float4*)(out + (blockIdx.x * W_IMG + 4 * t) * 3);
        o4[0] = make_float4(R[0], G[0], B[0], R[1]);
        o4[1] = make_float4(G[1], B[1], R[2], G[2]);
        o4[2] = make_float4(B[2], R[3], G[3], B[3]);
    }
}

extern "C" void kernel_launch(void* const* d_in, const int* in_sizes, int n_in,
                              void* d_out, int out_size) {
    const float* means  = nullptr;
    const float* cov    = nullptr;
    const float* opac   = nullptr;
    const float* colors = nullptr;
    for (int i = 0; i < n_in; i++) {
        switch (in_sizes[i]) {
            case NG * 2: means  = (const float*)d_in[i]; break;
            case NG * 4: cov    = (const float*)d_in[i]; break;
            case NG:     opac   = (const float*)d_in[i]; break;
            case NG * 3: colors = (const float*)d_in[i]; break;
            default: break;
        }
    }
    Render_75617194213733_kernel<<<H_IMG, 256>>>(means, cov, opac, colors,
                                                 (float*)d_out);
}

// round 17
// speedup vs baseline: 1.0332x; 1.0295x over previous
#include <cuda_runtime.h>

#define NG      512
#define W_IMG   256
#define H_IMG   256
#define NEG_HALF_LOG2E (-0.7213475204444817f)   // -0.5 * log2(e)
#define LOG2EPS (-13.0f)                        // skip if max alpha < 2^-13 (~1.2e-4)
// Error audit: measured sensitivity of the cull threshold is weak
// (-27 -> -16 raised rel_err only 2.8e-5 -> 3.1e-5); the dominant term is the
// threshold-independent dropped +1e-7 per culled gaussian (~5e-5). At -13 the
// boundary alpha mass adds ~<1e-4 rel — total stays >=6x under the 1e-3 gate.

__device__ __forceinline__ float ex2_approx(float x) {
    float y; asm("ex2.approx.f32 %0, %1;" : "=f"(y) : "f"(x)); return y;
}
__device__ __forceinline__ float lg2_approx(float x) {
    float y; asm("lg2.approx.f32 %0, %1;" : "=f"(y) : "f"(x)); return y;
}
__device__ __forceinline__ float rcp_approx(float x) {
    float y; asm("rcp.approx.f32 %0, %1;" : "=f"(y) : "f"(x)); return y;
}

// One block per row, 256 threads = 4 groups × 64; each thread composites an
// ordered quarter of the survivors for 4 adjacent pixels (second-difference
// exponent). Prep culls per (gaussian, x-half) with the clamped-vertex window
// test (vertex computed as (b+c)dy/(2d) — the normalization s cancels, so its
// rcp runs in parallel with rcp(det), shortening the prep critical path) and
// builds TWO ordered compacted lists (px[0,128) / px[128,256)); a warp's lanes
// lie entirely in one half, so the mainloop iterates only its half's list —
// no per-iteration vote. Global loads are front-batched for MLP; mainloop
// processes 2 gaussians per step (batched LDS). Partials combined exactly
// (compositing is an associative affine map).
__global__ __launch_bounds__(256) void Render_75617194213733_kernel(
    const float* __restrict__ means,    // [NG,2]
    const float* __restrict__ cov,      // [NG,2,2]
    const float* __restrict__ opac,     // [NG]
    const float* __restrict__ colors,   // [NG,3]
    float* __restrict__ out)            // [H,W,3]
{
    __shared__ float4 C[4 * NG];        // half0 at 0, half1 at 2*NG:
                                        // [2j]=(mx,ka,kb*dy,kd*dy^2+lop), [2j+1]=(cr,cg,cb,2ka)
    __shared__ float4 Ppart[4][3 * 64]; // per-pixel partials, groups 1..3
    __shared__ int    sCnt0[16], sCnt1[16];
    __shared__ int    sBase0[16], sBase1[16];
    __shared__ int    sM0, sM1;

    const int tid  = threadIdx.x;
    const int lane = tid & 31;
    const int warp = tid >> 5;
    const float py = (float)blockIdx.x + 0.5f;

    // ── Front-batched global loads for both gaussian chunks (max MLP).
    const int g0i = tid, g1i = tid + 256;
    float4 cv_[2];
    float2 mn_[2];
    float  op_[2];
    float  cr_[2], cg_[2], cb_[2];
    cv_[0] = ((const float4*)cov)[g0i];
    cv_[1] = ((const float4*)cov)[g1i];
    mn_[0] = ((const float2*)means)[g0i];
    mn_[1] = ((const float2*)means)[g1i];
    op_[0] = opac[g0i];
    op_[1] = opac[g1i];
    cr_[0] = colors[3 * g0i + 0]; cg_[0] = colors[3 * g0i + 1]; cb_[0] = colors[3 * g0i + 2];
    cr_[1] = colors[3 * g1i + 0]; cg_[1] = colors[3 * g1i + 1]; cb_[1] = colors[3 * g1i + 2];

    // ── Fused prep + per-half x-window cull (2 gaussians/thread).
    float4 A[2], B[2];
    bool   kp0[2], kp1[2];
    unsigned b0[2], b1[2];
#pragma unroll
    for (int c = 0; c < 2; c++) {
        float4 cv = cv_[c];
        float2 mn = mn_[c];
        float dy  = py - mn.y;
        // Independent MUFUs first — all three issue back-to-back:
        float rdet = rcp_approx(fmaf(cv.x, cv.w, -cv.y * cv.z));
        float rdd  = rcp_approx(cv.w + cv.w);          // 1/(2d): vertex, s-free
        float lop  = lg2_approx(op_[c]);
        float s   = NEG_HALF_LOG2E * rdet;
        float ka  = s * cv.w;                          // < 0
        float kb  = -s * (cv.y + cv.z);
        float kd  = s * cv.x;                          // < 0
        float kbdy = kb * dy;
        float c1   = fmaf(kd * dy, dy, lop);           // kd*dy^2 + log2(op)
        // vertex of m(dx)=ka*dx^2+kbdy*dx+c1:
        //   dx* = -kbdy/(2ka) = (b+c)*dy/(2d)  (s cancels; d>0 since SPD+0.3I)
        float dxv = (cv.y + cv.z) * dy * rdd;
        float d0 = fminf(fmaxf(dxv, 0.5f - mn.x),   127.5f - mn.x);
        float d1 = fminf(fmaxf(dxv, 128.5f - mn.x), 255.5f - mn.x);
        kp0[c] = fmaf(fmaf(ka, d0, kbdy), d0, c1) > LOG2EPS;
        kp1[c] = fmaf(fmaf(ka, d1, kbdy), d1, c1) > LOG2EPS;
        b0[c] = __ballot_sync(0xffffffffu, kp0[c]);
        b1[c] = __ballot_sync(0xffffffffu, kp1[c]);
        if (lane == 0) {
            sCnt0[c * 8 + warp] = __popc(b0[c]);
            sCnt1[c * 8 + warp] = __popc(b1[c]);
        }
        A[c] = make_float4(mn.x, ka, kbdy, c1);
        B[c] = make_float4(cr_[c], cg_[c], cb_[c], ka + ka);
    }
    __syncthreads();

    // ── Parallel shuffle scans: warp 0 -> half0 counts, warp 1 -> half1.
    if (warp < 2) {
        const int* cnt = warp ? sCnt1 : sCnt0;
        int* bas = warp ? sBase1 : sBase0;
        int c = (lane < 16) ? cnt[lane] : 0;
        int inc = c;
#pragma unroll
        for (int d = 1; d < 16; d <<= 1) {
            int n = __shfl_up_sync(0xffffffffu, inc, d);
            if (lane >= d) inc += n;
        }
        if (lane < 16) bas[lane] = inc - c;
        if (lane == 15) { if (warp) sM1 = inc; else sM0 = inc; }
    }
    __syncthreads();

#pragma unroll
    for (int c = 0; c < 2; c++) {
        const unsigned lm = (1u << lane) - 1u;
        if (kp0[c]) {
            int j = sBase0[c * 8 + warp] + __popc(b0[c] & lm);
            C[2 * j]     = A[c];
            C[2 * j + 1] = B[c];
        }
        if (kp1[c]) {
            int j = sBase1[c * 8 + warp] + __popc(b1[c] & lm);
            C[2 * NG + 2 * j]     = A[c];
            C[2 * NG + 2 * j + 1] = B[c];
        }
    }
    __syncthreads();

    // ── Mainloop: warp's lanes span one 128-px half; iterate that half's list.
    const int half  = warp & 1;                 // even warp ⇔ t<32 ⇔ px<128
    const int M     = half ? sM1 : sM0;
    const float4* __restrict__ Ch = C + half * (2 * NG);
    const int Mq    = (M + 3) >> 2;
    const int group = tid >> 6;
    const int t     = tid & 63;
    const int j0    = min(group * Mq, M);
    const int j1    = min(j0 + Mq, M);

    const float px = (float)(4 * t) + 0.5f;

    float T0 = 1.f, T1 = 1.f, T2 = 1.f, T3 = 1.f;
    float r0 = 0.f, g0 = 0.f, u0 = 0.f;
    float r1 = 0.f, g1 = 0.f, u1 = 0.f;
    float r2 = 0.f, g2 = 0.f, u2 = 0.f;
    float r3 = 0.f, g3 = 0.f, u3 = 0.f;

    int j = j0;
    for (; j + 1 < j1; j += 2) {
        // 4 × LDS.128 issued back-to-back (2× MLP on the LDS path).
        float4 paA = Ch[2 * j],     pbA = Ch[2 * j + 1];
        float4 paB = Ch[2 * j + 2], pbB = Ch[2 * j + 3];

        float dxA = px - paA.x;
        float t2A = fmaf(paA.y, dxA, paA.z);
        float m0A = fmaf(dxA, t2A, paA.w);
        float s0A = t2A + fmaf(paA.y, dxA, paA.y);
        float m1A = m0A + s0A;
        float s1A = s0A + pbA.w;
        float m2A = m1A + s1A;
        float m3A = m2A + s1A + pbA.w;

        float a0 = ex2_approx(m0A), a1 = ex2_approx(m1A);
        float a2 = ex2_approx(m2A), a3 = ex2_approx(m3A);
        float w0 = a0 * T0, w1 = a1 * T1, w2 = a2 * T2, w3 = a3 * T3;
        r0 = fmaf(w0, pbA.x, r0); g0 = fmaf(w0, pbA.y, g0); u0 = fmaf(w0, pbA.z, u0);
        r1 = fmaf(w1, pbA.x, r1); g1 = fmaf(w1, pbA.y, g1); u1 = fmaf(w1, pbA.z, u1);
        r2 = fmaf(w2, pbA.x, r2); g2 = fmaf(w2, pbA.y, g2); u2 = fmaf(w2, pbA.z, u2);
        r3 = fmaf(w3, pbA.x, r3); g3 = fmaf(w3, pbA.y, g3); u3 = fmaf(w3, pbA.z, u3);
        T0 *= 1.0000001f - a0;
        T1 *= 1.0000001f - a1;
        T2 *= 1.0000001f - a2;
        T3 *= 1.0000001f - a3;

        float dxB = px - paB.x;
        float t2B = fmaf(paB.y, dxB, paB.z);
        float m0B = fmaf(dxB, t2B, paB.w);
        float s0B = t2B + fmaf(paB.y, dxB, paB.y);
        float m1B = m0B + s0B;
        float s1B = s0B + pbB.w;
        float m2B = m1B + s1B;
        float m3B = m2B + s1B + pbB.w;

        float e0 = ex2_approx(m0B), e1 = ex2_approx(m1B);
        float e2 = ex2_approx(m2B), e3 = ex2_approx(m3B);
        float v0 = e0 * T0, v1 = e1 * T1, v2 = e2 * T2, v3 = e3 * T3;
        r0 = fmaf(v0, pbB.x, r0); g0 = fmaf(v0, pbB.y, g0); u0 = fmaf(v0, pbB.z, u0);
        r1 = fmaf(v1, pbB.x, r1); g1 = fmaf(v1, pbB.y, g1); u1 = fmaf(v1, pbB.z, u1);
        r2 = fmaf(v2, pbB.x, r2); g2 = fmaf(v2, pbB.y, g2); u2 = fmaf(v2, pbB.z, u2);
        r3 = fmaf(v3, pbB.x, r3); g3 = fmaf(v3, pbB.y, g3); u3 = fmaf(v3, pbB.z, u3);
        T0 *= 1.0000001f - e0;
        T1 *= 1.0000001f - e1;
        T2 *= 1.0000001f - e2;
        T3 *= 1.0000001f - e3;
    }
    if (j < j1) {
        float4 pa = Ch[2 * j], pb = Ch[2 * j + 1];
        float dx = px - pa.x;
        float t2 = fmaf(pa.y, dx, pa.z);
        float m0 = fmaf(dx, t2, pa.w);
        float s0 = t2 + fmaf(pa.y, dx, pa.y);
        float m1 = m0 + s0;
        float s1 = s0 + pb.w;
        float m2 = m1 + s1;
        float m3 = m2 + s1 + pb.w;
        float a0 = ex2_approx(m0), a1 = ex2_approx(m1);
        float a2 = ex2_approx(m2), a3 = ex2_approx(m3);
        float w0 = a0 * T0, w1 = a1 * T1, w2 = a2 * T2, w3 = a3 * T3;
        r0 = fmaf(w0, pb.x, r0); g0 = fmaf(w0, pb.y, g0); u0 = fmaf(w0, pb.z, u0);
        r1 = fmaf(w1, pb.x, r1); g1 = fmaf(w1, pb.y, g1); u1 = fmaf(w1, pb.z, u1);
        r2 = fmaf(w2, pb.x, r2); g2 = fmaf(w2, pb.y, g2); u2 = fmaf(w2, pb.z, u2);
        r3 = fmaf(w3, pb.x, r3); g3 = fmaf(w3, pb.y, g3); u3 = fmaf(w3, pb.z, u3);
        T0 *= 1.0000001f - a0;
        T1 *= 1.0000001f - a1;
        T2 *= 1.0000001f - a2;
        T3 *= 1.0000001f - a3;
    }

    // ── Exact segment combine: C = C_a + T_a * C_b (fold groups 3→2→1→0).
    if (group != 0) {
        int pi = (group - 1) * 64 + t;
        Ppart[0][pi] = make_float4(r0, g0, u0, T0);
        Ppart[1][pi] = make_float4(r1, g1, u1, T1);
        Ppart[2][pi] = make_float4(r2, g2, u2, T2);
        Ppart[3][pi] = make_float4(r3, g3, u3, T3);
    }
    __syncthreads();
    if (group == 0) {
        float rl[4] = {r0, r1, r2, r3};
        float gl[4] = {g0, g1, g2, g3};
        float bl[4] = {u0, u1, u2, u3};
        float Tl[4] = {T0, T1, T2, T3};
        float R[4], G[4], B[4];
#pragma unroll
        for (int p = 0; p < 4; p++) {
            float4 q1 = Ppart[p][t];
            float4 q2 = Ppart[p][64 + t];
            float4 q3 = Ppart[p][128 + t];
            float rr = fmaf(q2.w, q3.x, q2.x);
            float gg = fmaf(q2.w, q3.y, q2.y);
            float bb = fmaf(q2.w, q3.z, q2.z);
            rr = fmaf(q1.w, rr, q1.x);
            gg = fmaf(q1.w, gg, q1.y);
            bb = fmaf(q1.w, bb, q1.z);
            R[p] = fmaf(Tl[p], rr, rl[p]);
            G[p] = fmaf(Tl[p], gg, gl[p]);
            B[p] = fmaf(Tl[p], bb, bl[p]);
        }
        float4* o4 = (float4*)(out + (blockIdx.x * W_IMG + 4 * t) * 3);
        o4[0] = make_float4(R[0], G[0], B[0], R[1]);
        o4[1] = make_float4(G[1], B[1], R[2], G[2]);
        o4[2] = make_float4(B[2], R[3], G[3], B[3]);
    }
}

extern "C" void kernel_launch(void* const* d_in, const int* in_sizes, int n_in,
                              void* d_out, int out_size) {
    const float* means  = nullptr;
    const float* cov    = nullptr;
    const float* opac   = nullptr;
    const float* colors = nullptr;
    for (int i = 0; i < n_in; i++) {
        switch (in_sizes[i]) {
            case NG * 2: means  = (const float*)d_in[i]; break;
            case NG * 4: cov    = (const float*)d_in[i]; break;
            case NG:     opac   = (const float*)d_in[i]; break;
            case NG * 3: colors = (const float*)d_in[i]; break;
            default: break;
        }
    }
    Render_75617194213733_kernel<<<H_IMG, 256>>>(means, cov, opac, colors,
                                                 (float*)d_out);
}